// round 15
// baseline (speedup 1.0000x reference)
#include <cuda_runtime.h>
#include <cuda_bf16.h>
#include <math.h>
#include <stdint.h>

#define NV 32768
#define NE 524288
#define NH 128
#define NB 128
#define NPG 256
#define KF 640

typedef unsigned short u16;

// ---------------- helpers ----------------
__device__ __forceinline__ uint32_t smem_u32(const void* p) {
    uint32_t a;
    asm("{ .reg .u64 t; cvta.to.shared.u64 t, %1; cvt.u32.u64 %0, t; }" : "=r"(a) : "l"(p));
    return a;
}

#define LDM_X4(r0, r1, r2, r3, addr)                                         \
    asm volatile("ldmatrix.sync.aligned.m8n8.x4.shared.b16 {%0,%1,%2,%3}, [%4];" \
        : "=r"(r0), "=r"(r1), "=r"(r2), "=r"(r3) : "r"(addr))

#define MMA16816(d, a, b0, b1)                                               \
    asm volatile("mma.sync.aligned.m16n8k16.row.col.f32.bf16.bf16.f32 "      \
        "{%0,%1,%2,%3}, {%4,%5,%6,%7}, {%8,%9}, {%0,%1,%2,%3};"              \
        : "+f"((d)[0]), "+f"((d)[1]), "+f"((d)[2]), "+f"((d)[3])             \
        : "r"((a)[0]), "r"((a)[1]), "r"((a)[2]), "r"((a)[3]),                \
          "r"(b0), "r"(b1))

#define CP16(dst, src)                                                       \
    asm volatile("{ .reg .u64 g; cvta.to.global.u64 g, %1; "                 \
        "cp.async.ca.shared.global [%0], [g], 16; }"                         \
        :: "r"(dst), "l"(src) : "memory")
#define CP_COMMIT() asm volatile("cp.async.commit_group;" ::: "memory")
#define CP_WAIT1()  asm volatile("cp.async.wait_group 1;" ::: "memory")
#define CP_WAIT0()  asm volatile("cp.async.wait_group 0;" ::: "memory")

__device__ __forceinline__ void cvt2(float a, float b, uint32_t& hi, uint32_t& lo) {
    __nv_bfloat16 ha = __float2bfloat16_rn(a), hb = __float2bfloat16_rn(b);
    float ra = a - __bfloat162float(ha);
    float rb = b - __bfloat162float(hb);
    __nv_bfloat16 la = __float2bfloat16_rn(ra), lb = __float2bfloat16_rn(rb);
    u16 uha = *(u16*)&ha, uhb = *(u16*)&hb;
    u16 ula = *(u16*)&la, ulb = *(u16*)&lb;
    hi = ((uint32_t)uhb << 16) | uha;
    lo = ((uint32_t)ulb << 16) | ula;
}

__device__ __forceinline__ void wsplit(u16* ph, u16* pl, float v) {
    __nv_bfloat16 h = __float2bfloat16_rn(v);
    float r = v - __bfloat162float(h);
    __nv_bfloat16 l = __float2bfloat16_rn(r);
    *ph = *(u16*)&h; *pl = *(u16*)&l;
}

// ---------------- scratch ----------------
__device__ int   g_cnt[NV];
__device__ int   g_off[NV + 1];
__device__ int   g_cur[NV];
__device__ int   g_csr[NE];
__device__ float g_logd[NV];
__device__ float g_amp[NV];
__device__ float g_att[NV];
__device__ float g_avg;
__device__ float g_lossb[NB];
__device__ float g_zero128[NH];
__device__ float g_lbf[NH];      // fused bias: post_b@Wl + lin_b
__device__ float g_lb1f[NH];     // fused bias: post1_b@Wl1 + lin1_b
__device__ float g_Ap[NV * NH];
__device__ float g_Bp[NV * NH];
__device__ float g_c0[NV * NH];  // also scratch for fused Wf0 (fp32) during setup
__device__ float g_c1[NV * NH];  // also scratch for fused Wf1
__device__ float g_c2[NV * NH];  // also scratch for fused Wf2
__device__ float g_h1[NV * NH];  // also scratch for fused post1 weight [26,128]
__device__ float g_A1[NV * 2];
__device__ float g_B1[NV * 2];
__device__ float g_feat1[NV * 26];
// split bf16 planes
__device__ __align__(16) u16 g_sh[NV * NH];
__device__ __align__(16) u16 g_sl[NV * NH];
__device__ __align__(16) u16 g_fh[(size_t)NV * KF];
__device__ __align__(16) u16 g_fl[(size_t)NV * KF];
// weight planes (K-major) -- W0/W1/W2 hold the Wl-FUSED weights
__device__ __align__(16) u16 g_W0h[NH * KF],  g_W0l[NH * KF];
__device__ __align__(16) u16 g_W1h[NH * 512], g_W1l[NH * 512];
__device__ __align__(16) u16 g_W2h[NH * 512], g_W2l[NH * 512];
__device__ __align__(16) u16 g_WpAh[NH * NH], g_WpAl[NH * NH];
__device__ __align__(16) u16 g_WpBh[NH * NH], g_WpBl[NH * NH];
__device__ __align__(16) u16 g_Wr1h[NH * NH], g_Wr1l[NH * NH];

// ---------------- setup kernels ----------------
__global__ void k_zero() {
    int i = blockIdx.x * blockDim.x + threadIdx.x;
    if (i < NV) { g_cnt[i] = 0; g_cur[i] = 0; }
    if (i < NB) g_lossb[i] = 0.f;
    if (i < NH) g_zero128[i] = 0.f;
    if (i == 0) g_avg = 0.f;
}

__global__ void k_hist(const int* __restrict__ ei) {
    int e = blockIdx.x * blockDim.x + threadIdx.x;
    if (e < NE) atomicAdd(&g_cnt[ei[NE + e]], 1);
}

__global__ void k_scan() {
    __shared__ int sums[1024];
    int t = threadIdx.x;
    int base = t * 32;
    int loc[32];
    int s = 0;
#pragma unroll
    for (int i = 0; i < 32; i++) { loc[i] = s; s += g_cnt[base + i]; }
    sums[t] = s;
    __syncthreads();
    for (int d = 1; d < 1024; d <<= 1) {
        int v = (t >= d) ? sums[t - d] : 0;
        __syncthreads();
        sums[t] += v;
        __syncthreads();
    }
    int excl = sums[t] - s;
#pragma unroll
    for (int i = 0; i < 32; i++) g_off[base + i] = excl + loc[i];
    if (t == 1023) g_off[NV] = excl + s;
}

__global__ void k_scatter(const int* __restrict__ ei) {
    int e = blockIdx.x * blockDim.x + threadIdx.x;
    if (e < NE) {
        int d = ei[NE + e];
        int p = g_off[d] + atomicAdd(&g_cur[d], 1);
        g_csr[p] = ei[e];
    }
}

__global__ void k_degstat() {
    int v = blockIdx.x * blockDim.x + threadIdx.x;
    int d = g_cnt[v];
    float degc = fmaxf((float)d, 1.f);
    g_logd[v] = logf(degc + 1.f);
    float l = logf((float)d + 1.f);
#pragma unroll
    for (int s = 16; s; s >>= 1) l += __shfl_xor_sync(0xffffffffu, l, s);
    if ((threadIdx.x & 31) == 0) atomicAdd(&g_avg, l);
}

__global__ void k_ampatt() {
    int v = blockIdx.x * blockDim.x + threadIdx.x;
    float avg = g_avg / (float)NV;
    float logd = g_logd[v];
    g_amp[v] = logd / avg;
    g_att[v] = avg / logd;
}

// ---------------- weight fusion (fp32): C[k][n] = sum_m A[k][m]*B[m][n] -----
__global__ void k_wf(const float* __restrict__ A, const float* __restrict__ B,
                     float* __restrict__ C) {
    __shared__ float ar[128];
    int k = blockIdx.x, n = threadIdx.x;
    ar[n] = A[k * 128 + n];
    __syncthreads();
    float acc = 0.f;
#pragma unroll 16
    for (int m = 0; m < 128; m++) acc += ar[m] * B[m * 128 + n];
    C[k * 128 + n] = acc;
}

// fused bias: ob[n] = sum_m pb[m]*Wl[m][n] + lb[n]
__global__ void k_bf(const float* __restrict__ pb, const float* __restrict__ Wl,
                     const float* __restrict__ lb, float* __restrict__ ob) {
    int n = threadIdx.x;
    float acc = lb[n];
    for (int m = 0; m < 128; m++) acc += pb[m] * Wl[m * 128 + n];
    ob[n] = acc;
}

// ---------------- weight transpose+split ----------------
__global__ void k_tsplit(const float* __restrict__ W, u16* __restrict__ Wh,
                         u16* __restrict__ Wl, int K) {
    __shared__ float tile[32][33];
    int kb = blockIdx.x * 32, nb = blockIdx.y * 32;
    int tx = threadIdx.x, ty = threadIdx.y;
    for (int i = ty; i < 32; i += 8)
        tile[i][tx] = W[(kb + i) * NH + nb + tx];
    __syncthreads();
    for (int i = ty; i < 32; i += 8)
        wsplit(&Wh[(nb + i) * K + kb + tx], &Wl[(nb + i) * K + kb + tx], tile[tx][i]);
}

// ---------------- layer 1 (feature dim 2) ----------------
__global__ void k_pre1(const float* __restrict__ x, const float* __restrict__ w,
                       const float* __restrict__ b) {
    int v = blockIdx.x * blockDim.x + threadIdx.x;
    float x0 = x[2 * v], x1 = x[2 * v + 1];
    g_A1[2 * v + 0] = x0 * w[0] + x1 * w[2] + b[0];
    g_A1[2 * v + 1] = x0 * w[1] + x1 * w[3] + b[1];
    g_B1[2 * v + 0] = x0 * w[4] + x1 * w[6];
    g_B1[2 * v + 1] = x0 * w[5] + x1 * w[7];
}

__global__ void k_agg1(const float* __restrict__ x) {
    int v = blockIdx.x * blockDim.x + threadIdx.x;
    if (v >= NV) return;
    int beg = g_off[v], end = g_off[v + 1];
    float a0 = g_A1[2 * v], a1 = g_A1[2 * v + 1];
    float s0 = 0, s1 = 0, q0 = 0, q1 = 0;
    float mx0 = -3.4e38f, mx1 = -3.4e38f, mn0 = 3.4e38f, mn1 = 3.4e38f;
    for (int e = beg; e < end; e++) {
        int s = g_csr[e];
        float h0 = a0 + g_B1[2 * s];
        float h1 = a1 + g_B1[2 * s + 1];
        s0 += h0; s1 += h1; q0 += h0 * h0; q1 += h1 * h1;
        mx0 = fmaxf(mx0, h0); mx1 = fmaxf(mx1, h1);
        mn0 = fminf(mn0, h0); mn1 = fminf(mn1, h1);
    }
    int d = end - beg;
    float degc = d > 0 ? (float)d : 1.f;
    float m0 = s0 / degc, m1 = s1 / degc;
    float sd0 = sqrtf(fmaxf(q0 / degc - m0 * m0, 0.f) + 1e-5f);
    float sd1 = sqrtf(fmaxf(q1 / degc - m1 * m1, 0.f) + 1e-5f);
    if (d == 0) { mx0 = mx1 = mn0 = mn1 = 0.f; }
    float am = g_amp[v], at = g_att[v];
    float* fr = g_feat1 + v * 26;
    fr[0] = x[2 * v]; fr[1] = x[2 * v + 1];
    fr[2] = m0;  fr[3] = m1;  fr[4] = sd0;  fr[5] = sd1;
    fr[6] = mx0; fr[7] = mx1; fr[8] = mn0;  fr[9] = mn1;
    fr[10] = m0 * am;  fr[11] = m1 * am;  fr[12] = sd0 * am; fr[13] = sd1 * am;
    fr[14] = mx0 * am; fr[15] = mx1 * am; fr[16] = mn0 * am; fr[17] = mn1 * am;
    fr[18] = m0 * at;  fr[19] = m1 * at;  fr[20] = sd0 * at; fr[21] = sd1 * at;
    fr[22] = mx0 * at; fr[23] = mx1 * at; fr[24] = mn0 * at; fr[25] = mn1 * at;
}

// post1 with lin1 pre-fused weight (fp32 [26,128] in wf) -> state planes
__global__ void k_post1(const float* __restrict__ wf, const float* __restrict__ bf) {
    __shared__ float fr[26];
    int v = blockIdx.x;
    int c = threadIdx.x;
    if (c < 26) fr[c] = g_feat1[v * 26 + c];
    __syncthreads();
    float acc = bf[c];
#pragma unroll
    for (int k = 0; k < 26; k++) acc += fr[k] * wf[k * NH + c];
    wsplit(&g_sh[v * NH + c], &g_sl[v * NH + c], acc);
}

// ---------------- lean GEMM ----------------
// block 256 = 8 warps, warp tile 32x32: rb=(w&1)*32, cb=(w>>1)*32.
// MODE 0: fp32 out (+bias). MODE 1: fp32 out leaky.
// MODE 3: state = X0 + amp*X1 + att*acc + bias -> split planes.
template<int MODE>
__global__ void __launch_bounds__(256, 2) k_g(
    const u16* __restrict__ Ah, const u16* __restrict__ Al, int lda, int K,
    const u16* __restrict__ Bh, const u16* __restrict__ Bl,
    const float* __restrict__ bias,
    float* __restrict__ outf, u16* __restrict__ outh, u16* __restrict__ outl,
    const float* __restrict__ X0, const float* __restrict__ X1,
    const float* __restrict__ ampp, const float* __restrict__ attp) {
    constexpr int CHUNK = 30720;   // Ah 5120 | Al 5120 | Bh 10240 | Bl 10240
    extern __shared__ char dsm[];
    uint32_t sb = smem_u32(dsm);
    int t = threadIdx.x, w = t >> 5, lane = t & 31;
    int m0 = blockIdx.x * 64;
    int rb = (w & 1) * 32, cb = (w >> 1) * 32;
    float acc[2][4][4] = {};

    int arow = t >> 2, aseg = (t & 3) * 8;
    const u16* aHp = Ah + (size_t)(m0 + arow) * lda + aseg;
    const u16* aLp = Al + (size_t)(m0 + arow) * lda + aseg;
    uint32_t aso = (uint32_t)(arow * 40 + aseg) * 2;
    int brow = t >> 1, bseg = (t & 1) * 16;
    const u16* bHp = Bh + (size_t)brow * K + bseg;
    const u16* bLp = Bl + (size_t)brow * K + bseg;
    uint32_t bso = (uint32_t)(brow * 40 + bseg) * 2;

    int nch = K >> 5;
    auto issue = [&](int ch) {
        int k0 = ch << 5;
        uint32_t bb = sb + (uint32_t)(ch & 1) * CHUNK;
        CP16(bb + aso, aHp + k0);
        CP16(bb + 5120 + aso, aLp + k0);
        CP16(bb + 10240 + bso, bHp + k0);
        CP16(bb + 10240 + bso + 16, bHp + k0 + 8);
        CP16(bb + 20480 + bso, bLp + k0);
        CP16(bb + 20480 + bso + 16, bLp + k0 + 8);
        CP_COMMIT();
    };

    int frow = lane & 15, fcol = (lane >> 4) * 8;
    uint32_t ab0 = (uint32_t)((rb + frow) * 40 + fcol) * 2;
    uint32_t ab1 = (uint32_t)((rb + 16 + frow) * 40 + fcol) * 2;
    uint32_t nb0 = (uint32_t)((cb + frow) * 40 + fcol) * 2;
    uint32_t nb1 = (uint32_t)((cb + 16 + frow) * 40 + fcol) * 2;

    issue(0);
    for (int ch = 0; ch < nch; ch++) {
        if (ch + 1 < nch) { issue(ch + 1); CP_WAIT1(); }
        else { CP_WAIT0(); }
        __syncthreads();
        uint32_t bb = sb + (uint32_t)(ch & 1) * CHUNK;
#pragma unroll
        for (int kk = 0; kk < 2; kk++) {
            uint32_t ko = kk * 32;
            uint32_t ah[2][4], al[2][4];
            LDM_X4(ah[0][0], ah[0][1], ah[0][2], ah[0][3], bb + ab0 + ko);
            LDM_X4(ah[1][0], ah[1][1], ah[1][2], ah[1][3], bb + ab1 + ko);
            LDM_X4(al[0][0], al[0][1], al[0][2], al[0][3], bb + 5120 + ab0 + ko);
            LDM_X4(al[1][0], al[1][1], al[1][2], al[1][3], bb + 5120 + ab1 + ko);
#pragma unroll
            for (int n2 = 0; n2 < 2; n2++) {
                uint32_t bv = (n2 ? nb1 : nb0) + ko;
                uint32_t bh0, bh1, bh2, bh3, bl0, bl1, bl2, bl3;
                LDM_X4(bh0, bh1, bh2, bh3, bb + 10240 + bv);
                LDM_X4(bl0, bl1, bl2, bl3, bb + 20480 + bv);
#pragma unroll
                for (int rh = 0; rh < 2; rh++) {
                    MMA16816(acc[rh][n2 * 2 + 0], ah[rh], bh0, bh2);
                    MMA16816(acc[rh][n2 * 2 + 0], ah[rh], bl0, bl2);
                    MMA16816(acc[rh][n2 * 2 + 0], al[rh], bh0, bh2);
                    MMA16816(acc[rh][n2 * 2 + 1], ah[rh], bh1, bh3);
                    MMA16816(acc[rh][n2 * 2 + 1], ah[rh], bl1, bl3);
                    MMA16816(acc[rh][n2 * 2 + 1], al[rh], bh1, bh3);
                }
            }
        }
        __syncthreads();
    }

    // epilogue: direct writes
    int qr = lane >> 2;
    int cb2 = (lane & 3) * 2;
    float amv[2][2], atv[2][2];
    if (MODE == 3) {
#pragma unroll
        for (int rh = 0; rh < 2; rh++)
#pragma unroll
            for (int q = 0; q < 2; q++) {
                int row = m0 + rb + rh * 16 + qr + q * 8;
                amv[rh][q] = ampp[row];
                atv[rh][q] = attp[row];
            }
    }
#pragma unroll
    for (int rh = 0; rh < 2; rh++)
#pragma unroll
        for (int g = 0; g < 4; g++) {
            int col0 = cb + (g >> 1) * 16 + (g & 1) * 8 + cb2;
            float b0 = __ldg(&bias[col0]), b1 = __ldg(&bias[col0 + 1]);
            float v0 = acc[rh][g][0] + b0, v1 = acc[rh][g][1] + b1;
            float v2 = acc[rh][g][2] + b0, v3 = acc[rh][g][3] + b1;
            size_t o0 = (size_t)(m0 + rb + rh * 16 + qr) * 128 + col0;
            size_t o8 = o0 + 8 * 128;
            if (MODE == 3) {
                float2 x00 = *(const float2*)(X0 + o0);
                float2 x08 = *(const float2*)(X0 + o8);
                float2 x10 = *(const float2*)(X1 + o0);
                float2 x18 = *(const float2*)(X1 + o8);
                // v = c0 + amp*c1 + att*acc + bias'
                v0 = x00.x + amv[rh][0] * x10.x + atv[rh][0] * acc[rh][g][0] + b0;
                v1 = x00.y + amv[rh][0] * x10.y + atv[rh][0] * acc[rh][g][1] + b1;
                v2 = x08.x + amv[rh][1] * x18.x + atv[rh][1] * acc[rh][g][2] + b0;
                v3 = x08.y + amv[rh][1] * x18.y + atv[rh][1] * acc[rh][g][3] + b1;
                uint32_t h01, l01, h23, l23;
                cvt2(v0, v1, h01, l01);
                cvt2(v2, v3, h23, l23);
                *(uint32_t*)(outh + o0) = h01; *(uint32_t*)(outl + o0) = l01;
                *(uint32_t*)(outh + o8) = h23; *(uint32_t*)(outl + o8) = l23;
            } else {
                if (MODE == 1) {
                    if (v0 < 0.f) v0 *= 0.01f;
                    if (v1 < 0.f) v1 *= 0.01f;
                    if (v2 < 0.f) v2 *= 0.01f;
                    if (v3 < 0.f) v3 *= 0.01f;
                }
                float2 p0 = {v0, v1}, p8 = {v2, v3};
                *(float2*)(outf + o0) = p0;
                *(float2*)(outf + o8) = p8;
            }
        }
}

// ---------------- aggregation ----------------
__global__ void __launch_bounds__(128) k_agg() {
    __shared__ int s_src[128];
    int v = blockIdx.x;
    int f = threadIdx.x;
    int beg = g_off[v], end = g_off[v + 1];
    float a = g_Ap[v * NH + f];
    float sum = 0.f, sq = 0.f, mx = -3.4e38f, mn = 3.4e38f;
    for (int base = beg; base < end; base += 128) {
        int n = min(128, end - base);
        if (f < n) s_src[f] = g_csr[base + f];
        __syncthreads();
        int e = 0;
        for (; e + 4 <= n; e += 4) {
            int i0 = s_src[e], i1 = s_src[e + 1], i2 = s_src[e + 2], i3 = s_src[e + 3];
            float h0 = a + g_Bp[i0 * NH + f];
            float h1 = a + g_Bp[i1 * NH + f];
            float h2 = a + g_Bp[i2 * NH + f];
            float h3 = a + g_Bp[i3 * NH + f];
            sum += h0 + h1 + h2 + h3;
            sq += h0 * h0 + h1 * h1 + h2 * h2 + h3 * h3;
            mx = fmaxf(mx, fmaxf(fmaxf(h0, h1), fmaxf(h2, h3)));
            mn = fminf(mn, fminf(fminf(h0, h1), fminf(h2, h3)));
        }
        for (; e < n; e++) {
            float h = a + g_Bp[s_src[e] * NH + f];
            sum += h; sq += h * h; mx = fmaxf(mx, h); mn = fminf(mn, h);
        }
        __syncthreads();
    }
    int d = end - beg;
    float degc = d > 0 ? (float)d : 1.f;
    float mean = sum / degc;
    float stdv = sqrtf(fmaxf(sq / degc - mean * mean, 0.f) + 1e-5f);
    if (d == 0) { mx = 0.f; mn = 0.f; }
    size_t fb = (size_t)v * KF;
    g_fh[fb + f] = g_sh[v * NH + f];
    g_fl[fb + f] = g_sl[v * NH + f];
    wsplit(&g_fh[fb + 128 + f], &g_fl[fb + 128 + f], mean);
    wsplit(&g_fh[fb + 256 + f], &g_fl[fb + 256 + f], stdv);
    wsplit(&g_fh[fb + 384 + f], &g_fl[fb + 384 + f], mx);
    wsplit(&g_fh[fb + 512 + f], &g_fl[fb + 512 + f], mn);
}

// ---------------- readout tail ----------------
__global__ void __launch_bounds__(256) k_readout(const float* __restrict__ r2w,
                                                 const float* __restrict__ r2b,
                                                 const float* __restrict__ r3w,
                                                 const float* __restrict__ r3b,
                                                 const float* __restrict__ tgt,
                                                 float* __restrict__ out) {
    __shared__ float w2[128 * 8];
    int t = threadIdx.x;
    for (int i = t; i < 128 * 8; i += 256) w2[i] = r2w[i];
    __syncthreads();
    int warp = t >> 5, lane = t & 31;
    int v = blockIdx.x * 8 + warp;
    const float* h1 = g_h1 + v * NH;
    float p[8] = {0, 0, 0, 0, 0, 0, 0, 0};
    for (int k = lane; k < 128; k += 32) {
        float hv = h1[k];
#pragma unroll
        for (int j = 0; j < 8; j++) p[j] += hv * w2[k * 8 + j];
    }
#pragma unroll
    for (int j = 0; j < 8; j++)
#pragma unroll
        for (int s = 16; s; s >>= 1) p[j] += __shfl_xor_sync(0xffffffffu, p[j], s);
    if (lane == 0) {
        float h2[8];
#pragma unroll
        for (int j = 0; j < 8; j++) {
            float x = p[j] + r2b[j];
            h2[j] = x < 0.f ? 0.01f * x : x;
        }
        float err = 0.f;
#pragma unroll
        for (int c = 0; c < 3; c++) {
            float o = r3b[c];
#pragma unroll
            for (int j = 0; j < 8; j++) o += h2[j] * r3w[j * 3 + c];
            if (o < 0.f) o *= 0.01f;
            out[v * 3 + c] = o;
            float dd = o - tgt[v * 3 + c];
            err += dd * dd;
        }
        atomicAdd(&g_lossb[v >> 8], err);
    }
}

__global__ void k_loss(float* __restrict__ out) {
    __shared__ float s[128];
    int b = threadIdx.x;
    float l = g_lossb[b] / (float)(NPG * 3);
    out[NV * 3 + 1 + b] = l;
    s[b] = l;
    __syncthreads();
    for (int d = 64; d; d >>= 1) {
        if (b < d) s[b] += s[b + d];
        __syncthreads();
    }
    if (b == 0) out[NV * 3] = s[0] / (float)NB;
}

// ---------------- host ----------------
template <typename T>
static void* symv(T& s) { void* p = nullptr; cudaGetSymbolAddress(&p, s); return p; }

extern "C" void kernel_launch(void* const* d_in, const int* in_sizes, int n_in,
                              void* d_out, int out_size) {
    const float* x       = (const float*)d_in[0];
    const int*   ei      = (const int*)d_in[1];
    const float* tgt_n   = (const float*)d_in[2];
    const float* pre1_w  = (const float*)d_in[4];
    const float* pre1_b  = (const float*)d_in[5];
    const float* post1_w = (const float*)d_in[6];
    const float* post1_b = (const float*)d_in[7];
    const float* lin1_w  = (const float*)d_in[8];
    const float* lin1_b  = (const float*)d_in[9];
    const float* pre_w   = (const float*)d_in[10];
    const float* pre_b   = (const float*)d_in[11];
    const float* post_w  = (const float*)d_in[12];
    const float* post_b  = (const float*)d_in[13];
    const float* lin_w   = (const float*)d_in[14];
    const float* lin_b   = (const float*)d_in[15];
    const float* r1_w    = (const float*)d_in[16];
    const float* r1_b    = (const float*)d_in[17];
    const float* r2_w    = (const float*)d_in[18];
    const float* r2_b    = (const float*)d_in[19];
    const float* r3_w    = (const float*)d_in[20];
    const float* r3_b    = (const float*)d_in[21];
    float* out = (float*)d_out;

    float* p_Ap  = (float*)symv(g_Ap);
    float* p_Bp  = (float*)symv(g_Bp);
    float* p_c0  = (float*)symv(g_c0);
    float* p_c1  = (float*)symv(g_c1);
    float* p_c2  = (float*)symv(g_c2);
    float* p_h1  = (float*)symv(g_h1);
    float* p_amp = (float*)symv(g_amp);
    float* p_att = (float*)symv(g_att);
    float* p_z   = (float*)symv(g_zero128);
    float* p_lbf  = (float*)symv(g_lbf);
    float* p_lb1f = (float*)symv(g_lb1f);
    u16* p_sh  = (u16*)symv(g_sh);   u16* p_sl  = (u16*)symv(g_sl);
    u16* p_fh  = (u16*)symv(g_fh);   u16* p_fl  = (u16*)symv(g_fl);
    u16* p_W0h = (u16*)symv(g_W0h);  u16* p_W0l = (u16*)symv(g_W0l);
    u16* p_W1h = (u16*)symv(g_W1h);  u16* p_W1l = (u16*)symv(g_W1l);
    u16* p_W2h = (u16*)symv(g_W2h);  u16* p_W2l = (u16*)symv(g_W2l);
    u16* p_WpAh = (u16*)symv(g_WpAh); u16* p_WpAl = (u16*)symv(g_WpAl);
    u16* p_WpBh = (u16*)symv(g_WpBh); u16* p_WpBl = (u16*)symv(g_WpBl);
    u16* p_Wr1h = (u16*)symv(g_Wr1h); u16* p_Wr1l = (u16*)symv(g_Wr1l);

    const int SMG = 61440;   // double-buffered 2*30720
    cudaFuncSetAttribute(k_g<0>, cudaFuncAttributeMaxDynamicSharedMemorySize, SMG);
    cudaFuncSetAttribute(k_g<1>, cudaFuncAttributeMaxDynamicSharedMemorySize, SMG);
    cudaFuncSetAttribute(k_g<3>, cudaFuncAttributeMaxDynamicSharedMemorySize, SMG);

    // graph setup
    k_zero<<<NV / 256, 256>>>();
    k_hist<<<NE / 256, 256>>>(ei);
    k_scan<<<1, 1024>>>();
    k_scatter<<<NE / 256, 256>>>(ei);
    k_degstat<<<NV / 256, 256>>>();
    k_ampatt<<<NV / 256, 256>>>();

    // weight fusion: Wf_i = Wi @ lin_w (fp32, into c-buffers as scratch);
    // post1 fused with lin1 (into h1 scratch); fused biases.
    k_wf<<<KF, 128>>>(post_w, lin_w, p_c0);                 // Wf0 [640,128]
    k_wf<<<512, 128>>>(post_w + 640 * NH, lin_w, p_c1);     // Wf1 [512,128]
    k_wf<<<512, 128>>>(post_w + 1152 * NH, lin_w, p_c2);    // Wf2 [512,128]
    k_wf<<<26, 128>>>(post1_w, lin1_w, p_h1);               // Wp1f [26,128]
    k_bf<<<1, 128>>>(post_b, lin_w, lin_b, p_lbf);
    k_bf<<<1, 128>>>(post1_b, lin1_w, lin1_b, p_lb1f);

    // weight transposes + splits
    dim3 tb(32, 8);
    k_tsplit<<<dim3(4, 4), tb>>>(pre_w, p_WpAh, p_WpAl, NH);
    k_tsplit<<<dim3(4, 4), tb>>>(pre_w + NH * NH, p_WpBh, p_WpBl, NH);
    k_tsplit<<<dim3(KF / 32, 4), tb>>>(p_c0, p_W0h, p_W0l, KF);
    k_tsplit<<<dim3(16, 4), tb>>>(p_c1, p_W1h, p_W1l, 512);
    k_tsplit<<<dim3(16, 4), tb>>>(p_c2, p_W2h, p_W2l, 512);
    k_tsplit<<<dim3(4, 4), tb>>>(r1_w, p_Wr1h, p_Wr1l, NH);

    // layer 1 (post1 fused with lin1 -> state planes directly)
    k_pre1<<<NV / 256, 256>>>(x, pre1_w, pre1_b);
    k_agg1<<<NV / 256, 256>>>(x);
    k_post1<<<NV, 128>>>(p_h1, p_lb1f);

    // 3 propagation layers (lin GEMM algebraically eliminated)
    for (int p = 0; p < 3; p++) {
        k_g<0><<<NV / 64, 256, SMG>>>(p_sh, p_sl, NH, NH, p_WpAh, p_WpAl, pre_b,
                                      p_Ap, 0, 0, 0, 0, 0, 0);
        k_g<0><<<NV / 64, 256, SMG>>>(p_sh, p_sl, NH, NH, p_WpBh, p_WpBl, p_z,
                                      p_Bp, 0, 0, 0, 0, 0, 0);
        k_agg<<<NV, 128>>>();
        k_g<0><<<NV / 64, 256, SMG>>>(p_fh, p_fl, KF, KF, p_W0h, p_W0l, p_z,
                                      p_c0, 0, 0, 0, 0, 0, 0);
        k_g<0><<<NV / 64, 256, SMG>>>(p_fh + 128, p_fl + 128, KF, 512,
                                      p_W1h, p_W1l, p_z, p_c1, 0, 0, 0, 0, 0, 0);
        k_g<3><<<NV / 64, 256, SMG>>>(p_fh + 128, p_fl + 128, KF, 512,
                                      p_W2h, p_W2l, p_lbf, 0, p_sh, p_sl,
                                      p_c0, p_c1, p_amp, p_att);
    }

    // readout
    k_g<1><<<NV / 64, 256, SMG>>>(p_sh, p_sl, NH, NH, p_Wr1h, p_Wr1l, r1_b,
                                  p_h1, 0, 0, 0, 0, 0, 0);
    k_readout<<<NV / 8, 256>>>(r2_w, r2_b, r3_w, r3_b, tgt_n, out);
    k_loss<<<1, 128>>>(out);

    (void)in_sizes; (void)n_in; (void)out_size;
}

// round 16
// speedup vs baseline: 1.2268x; 1.2268x over previous
#include <cuda_runtime.h>
#include <cuda_fp16.h>
#include <math.h>
#include <stdint.h>

#define NV 32768
#define NE 524288
#define NH 128
#define NB 128
#define NPG 256
#define KF 640

typedef unsigned short u16;

// ---------------- helpers ----------------
__device__ __forceinline__ uint32_t smem_u32(const void* p) {
    uint32_t a;
    asm("{ .reg .u64 t; cvta.to.shared.u64 t, %1; cvt.u32.u64 %0, t; }" : "=r"(a) : "l"(p));
    return a;
}

#define LDM_X4(r0, r1, r2, r3, addr)                                         \
    asm volatile("ldmatrix.sync.aligned.m8n8.x4.shared.b16 {%0,%1,%2,%3}, [%4];" \
        : "=r"(r0), "=r"(r1), "=r"(r2), "=r"(r3) : "r"(addr))

#define MMA16816(d, a, b0, b1)                                               \
    asm volatile("mma.sync.aligned.m16n8k16.row.col.f32.f16.f16.f32 "       \
        "{%0,%1,%2,%3}, {%4,%5,%6,%7}, {%8,%9}, {%0,%1,%2,%3};"              \
        : "+f"((d)[0]), "+f"((d)[1]), "+f"((d)[2]), "+f"((d)[3])             \
        : "r"((a)[0]), "r"((a)[1]), "r"((a)[2]), "r"((a)[3]),                \
          "r"(b0), "r"(b1))

#define CP16(dst, src)                                                       \
    asm volatile("{ .reg .u64 g; cvta.to.global.u64 g, %1; "                 \
        "cp.async.ca.shared.global [%0], [g], 16; }"                         \
        :: "r"(dst), "l"(src) : "memory")
#define CP_COMMIT() asm volatile("cp.async.commit_group;" ::: "memory")
#define CP_WAIT1()  asm volatile("cp.async.wait_group 1;" ::: "memory")
#define CP_WAIT0()  asm volatile("cp.async.wait_group 0;" ::: "memory")

// fp16 2-term split of a pair of floats -> packed (hi, lo)
__device__ __forceinline__ void cvt2(float a, float b, uint32_t& hi, uint32_t& lo) {
    __half ha = __float2half_rn(a), hb = __float2half_rn(b);
    float ra = a - __half2float(ha);
    float rb = b - __half2float(hb);
    __half la = __float2half_rn(ra), lb = __float2half_rn(rb);
    u16 uha = *(u16*)&ha, uhb = *(u16*)&hb;
    u16 ula = *(u16*)&la, ulb = *(u16*)&lb;
    hi = ((uint32_t)uhb << 16) | uha;
    lo = ((uint32_t)ulb << 16) | ula;
}

__device__ __forceinline__ void wsplit(u16* ph, u16* pl, float v) {
    __half h = __float2half_rn(v);
    float r = v - __half2float(h);
    __half l = __float2half_rn(r);
    *ph = *(u16*)&h; *pl = *(u16*)&l;
}

__device__ __forceinline__ u16 w1(float v) {
    __half h = __float2half_rn(v);
    return *(u16*)&h;
}

// ---------------- scratch ----------------
__device__ int   g_cnt[NV];
__device__ int   g_off[NV + 1];
__device__ int   g_cur[NV];
__device__ int   g_csr[NE];
__device__ float g_logd[NV];
__device__ float g_amp[NV];
__device__ float g_att[NV];
__device__ float g_avg;
__device__ float g_lossb[NB];
__device__ float g_zero128[NH];
__device__ float g_lbf[NH];
__device__ float g_lb1f[NH];
__device__ float g_Ap[NV * NH];
__device__ float g_Bp[NV * NH];
__device__ float g_c0[NV * NH];   // scratch for fused Wf0 during setup
__device__ float g_c1[NV * NH];
__device__ float g_c2[NV * NH];
__device__ float g_h1[NV * NH];   // scratch for fused post1 weight
__device__ float g_A1[NV * 2];
__device__ float g_B1[NV * 2];
__device__ float g_feat1[NV * 26];
// fp16 split planes (activations)
__device__ __align__(16) u16 g_sh[NV * NH];
__device__ __align__(16) u16 g_sl[NV * NH];
__device__ __align__(16) u16 g_fh[(size_t)NV * KF];
__device__ __align__(16) u16 g_fl[(size_t)NV * KF];
// weight planes (K-major, single fp16) -- W0/W1/W2 are Wl-FUSED
__device__ __align__(16) u16 g_W0h[NH * KF];
__device__ __align__(16) u16 g_W1h[NH * 512];
__device__ __align__(16) u16 g_W2h[NH * 512];
__device__ __align__(16) u16 g_WpAh[NH * NH];
__device__ __align__(16) u16 g_WpBh[NH * NH];
__device__ __align__(16) u16 g_Wr1h[NH * NH];

// ---------------- setup kernels ----------------
__global__ void k_zero() {
    int i = blockIdx.x * blockDim.x + threadIdx.x;
    if (i < NV) { g_cnt[i] = 0; g_cur[i] = 0; }
    if (i < NB) g_lossb[i] = 0.f;
    if (i < NH) g_zero128[i] = 0.f;
    if (i == 0) g_avg = 0.f;
}

__global__ void k_hist(const int* __restrict__ ei) {
    int e = blockIdx.x * blockDim.x + threadIdx.x;
    if (e < NE) atomicAdd(&g_cnt[ei[NE + e]], 1);
}

__global__ void k_scan() {
    __shared__ int sums[1024];
    int t = threadIdx.x;
    int base = t * 32;
    int loc[32];
    int s = 0;
#pragma unroll
    for (int i = 0; i < 32; i++) { loc[i] = s; s += g_cnt[base + i]; }
    sums[t] = s;
    __syncthreads();
    for (int d = 1; d < 1024; d <<= 1) {
        int v = (t >= d) ? sums[t - d] : 0;
        __syncthreads();
        sums[t] += v;
        __syncthreads();
    }
    int excl = sums[t] - s;
#pragma unroll
    for (int i = 0; i < 32; i++) g_off[base + i] = excl + loc[i];
    if (t == 1023) g_off[NV] = excl + s;
}

__global__ void k_scatter(const int* __restrict__ ei) {
    int e = blockIdx.x * blockDim.x + threadIdx.x;
    if (e < NE) {
        int d = ei[NE + e];
        int p = g_off[d] + atomicAdd(&g_cur[d], 1);
        g_csr[p] = ei[e];
    }
}

__global__ void k_degstat() {
    int v = blockIdx.x * blockDim.x + threadIdx.x;
    int d = g_cnt[v];
    float degc = fmaxf((float)d, 1.f);
    g_logd[v] = logf(degc + 1.f);
    float l = logf((float)d + 1.f);
#pragma unroll
    for (int s = 16; s; s >>= 1) l += __shfl_xor_sync(0xffffffffu, l, s);
    if ((threadIdx.x & 31) == 0) atomicAdd(&g_avg, l);
}

__global__ void k_ampatt() {
    int v = blockIdx.x * blockDim.x + threadIdx.x;
    float avg = g_avg / (float)NV;
    float logd = g_logd[v];
    g_amp[v] = logd / avg;
    g_att[v] = avg / logd;
}

// ---------------- weight fusion (fp32) ----------------
__global__ void k_wf(const float* __restrict__ A, const float* __restrict__ B,
                     float* __restrict__ C) {
    __shared__ float ar[128];
    int k = blockIdx.x, n = threadIdx.x;
    ar[n] = A[k * 128 + n];
    __syncthreads();
    float acc = 0.f;
#pragma unroll 16
    for (int m = 0; m < 128; m++) acc += ar[m] * B[m * 128 + n];
    C[k * 128 + n] = acc;
}

__global__ void k_bf(const float* __restrict__ pb, const float* __restrict__ Wl,
                     const float* __restrict__ lb, float* __restrict__ ob) {
    int n = threadIdx.x;
    float acc = lb[n];
    for (int m = 0; m < 128; m++) acc += pb[m] * Wl[m * 128 + n];
    ob[n] = acc;
}

// ---------------- weight transpose + fp16 convert (single plane) -------------
__global__ void k_tsplit(const float* __restrict__ W, u16* __restrict__ Wh, int K) {
    __shared__ float tile[32][33];
    int kb = blockIdx.x * 32, nb = blockIdx.y * 32;
    int tx = threadIdx.x, ty = threadIdx.y;
    for (int i = ty; i < 32; i += 8)
        tile[i][tx] = W[(kb + i) * NH + nb + tx];
    __syncthreads();
    for (int i = ty; i < 32; i += 8)
        Wh[(nb + i) * K + kb + tx] = w1(tile[tx][i]);
}

// ---------------- layer 1 (feature dim 2) ----------------
__global__ void k_pre1(const float* __restrict__ x, const float* __restrict__ w,
                       const float* __restrict__ b) {
    int v = blockIdx.x * blockDim.x + threadIdx.x;
    float x0 = x[2 * v], x1 = x[2 * v + 1];
    g_A1[2 * v + 0] = x0 * w[0] + x1 * w[2] + b[0];
    g_A1[2 * v + 1] = x0 * w[1] + x1 * w[3] + b[1];
    g_B1[2 * v + 0] = x0 * w[4] + x1 * w[6];
    g_B1[2 * v + 1] = x0 * w[5] + x1 * w[7];
}

__global__ void k_agg1(const float* __restrict__ x) {
    int v = blockIdx.x * blockDim.x + threadIdx.x;
    if (v >= NV) return;
    int beg = g_off[v], end = g_off[v + 1];
    float a0 = g_A1[2 * v], a1 = g_A1[2 * v + 1];
    float s0 = 0, s1 = 0, q0 = 0, q1 = 0;
    float mx0 = -3.4e38f, mx1 = -3.4e38f, mn0 = 3.4e38f, mn1 = 3.4e38f;
    for (int e = beg; e < end; e++) {
        int s = g_csr[e];
        float h0 = a0 + g_B1[2 * s];
        float h1 = a1 + g_B1[2 * s + 1];
        s0 += h0; s1 += h1; q0 += h0 * h0; q1 += h1 * h1;
        mx0 = fmaxf(mx0, h0); mx1 = fmaxf(mx1, h1);
        mn0 = fminf(mn0, h0); mn1 = fminf(mn1, h1);
    }
    int d = end - beg;
    float degc = d > 0 ? (float)d : 1.f;
    float m0 = s0 / degc, m1 = s1 / degc;
    float sd0 = sqrtf(fmaxf(q0 / degc - m0 * m0, 0.f) + 1e-5f);
    float sd1 = sqrtf(fmaxf(q1 / degc - m1 * m1, 0.f) + 1e-5f);
    if (d == 0) { mx0 = mx1 = mn0 = mn1 = 0.f; }
    float am = g_amp[v], at = g_att[v];
    float* fr = g_feat1 + v * 26;
    fr[0] = x[2 * v]; fr[1] = x[2 * v + 1];
    fr[2] = m0;  fr[3] = m1;  fr[4] = sd0;  fr[5] = sd1;
    fr[6] = mx0; fr[7] = mx1; fr[8] = mn0;  fr[9] = mn1;
    fr[10] = m0 * am;  fr[11] = m1 * am;  fr[12] = sd0 * am; fr[13] = sd1 * am;
    fr[14] = mx0 * am; fr[15] = mx1 * am; fr[16] = mn0 * am; fr[17] = mn1 * am;
    fr[18] = m0 * at;  fr[19] = m1 * at;  fr[20] = sd0 * at; fr[21] = sd1 * at;
    fr[22] = mx0 * at; fr[23] = mx1 * at; fr[24] = mn0 * at; fr[25] = mn1 * at;
}

__global__ void k_post1(const float* __restrict__ wf, const float* __restrict__ bf) {
    __shared__ float fr[26];
    int v = blockIdx.x;
    int c = threadIdx.x;
    if (c < 26) fr[c] = g_feat1[v * 26 + c];
    __syncthreads();
    float acc = bf[c];
#pragma unroll
    for (int k = 0; k < 26; k++) acc += fr[k] * wf[k * NH + c];
    wsplit(&g_sh[v * NH + c], &g_sl[v * NH + c], acc);
}

// ---------------- lean GEMM (fp16: A 2-term split, B single plane) -----------
// block 256 = 8 warps, warp tile 32x32. 2 MMAs per logical MMA.
// MODE 0: fp32 out (+bias). MODE 1: fp32 out leaky.
// MODE 3: state = X0 + amp*X1 + att*acc + bias -> split planes.
template<int MODE>
__global__ void __launch_bounds__(256, 2) k_g(
    const u16* __restrict__ Ah, const u16* __restrict__ Al, int lda, int K,
    const u16* __restrict__ Bh,
    const float* __restrict__ bias,
    float* __restrict__ outf, u16* __restrict__ outh, u16* __restrict__ outl,
    const float* __restrict__ X0, const float* __restrict__ X1,
    const float* __restrict__ ampp, const float* __restrict__ attp) {
    constexpr int CHUNK = 20480;   // Ah 5120 | Al 5120 | B 10240
    extern __shared__ char dsm[];
    uint32_t sb = smem_u32(dsm);
    int t = threadIdx.x, w = t >> 5, lane = t & 31;
    int m0 = blockIdx.x * 64;
    int rb = (w & 1) * 32, cb = (w >> 1) * 32;
    float acc[2][4][4] = {};

    int arow = t >> 2, aseg = (t & 3) * 8;
    const u16* aHp = Ah + (size_t)(m0 + arow) * lda + aseg;
    const u16* aLp = Al + (size_t)(m0 + arow) * lda + aseg;
    uint32_t aso = (uint32_t)(arow * 40 + aseg) * 2;
    int brow = t >> 1, bseg = (t & 1) * 16;
    const u16* bHp = Bh + (size_t)brow * K + bseg;
    uint32_t bso = (uint32_t)(brow * 40 + bseg) * 2;

    int nch = K >> 5;
    auto issue = [&](int ch) {
        int k0 = ch << 5;
        uint32_t bb = sb + (uint32_t)(ch & 1) * CHUNK;
        CP16(bb + aso, aHp + k0);
        CP16(bb + 5120 + aso, aLp + k0);
        CP16(bb + 10240 + bso, bHp + k0);
        CP16(bb + 10240 + bso + 16, bHp + k0 + 8);
        CP_COMMIT();
    };

    int frow = lane & 15, fcol = (lane >> 4) * 8;
    uint32_t ab0 = (uint32_t)((rb + frow) * 40 + fcol) * 2;
    uint32_t ab1 = (uint32_t)((rb + 16 + frow) * 40 + fcol) * 2;
    uint32_t nb0 = (uint32_t)((cb + frow) * 40 + fcol) * 2;
    uint32_t nb1 = (uint32_t)((cb + 16 + frow) * 40 + fcol) * 2;

    issue(0);
    for (int ch = 0; ch < nch; ch++) {
        if (ch + 1 < nch) { issue(ch + 1); CP_WAIT1(); }
        else { CP_WAIT0(); }
        __syncthreads();
        uint32_t bb = sb + (uint32_t)(ch & 1) * CHUNK;
#pragma unroll
        for (int kk = 0; kk < 2; kk++) {
            uint32_t ko = kk * 32;
            uint32_t ah[2][4], al[2][4];
            LDM_X4(ah[0][0], ah[0][1], ah[0][2], ah[0][3], bb + ab0 + ko);
            LDM_X4(ah[1][0], ah[1][1], ah[1][2], ah[1][3], bb + ab1 + ko);
            LDM_X4(al[0][0], al[0][1], al[0][2], al[0][3], bb + 5120 + ab0 + ko);
            LDM_X4(al[1][0], al[1][1], al[1][2], al[1][3], bb + 5120 + ab1 + ko);
#pragma unroll
            for (int n2 = 0; n2 < 2; n2++) {
                uint32_t bv = (n2 ? nb1 : nb0) + ko;
                uint32_t bh0, bh1, bh2, bh3;
                LDM_X4(bh0, bh1, bh2, bh3, bb + 10240 + bv);
#pragma unroll
                for (int rh = 0; rh < 2; rh++) {
                    MMA16816(acc[rh][n2 * 2 + 0], ah[rh], bh0, bh2);
                    MMA16816(acc[rh][n2 * 2 + 0], al[rh], bh0, bh2);
                    MMA16816(acc[rh][n2 * 2 + 1], ah[rh], bh1, bh3);
                    MMA16816(acc[rh][n2 * 2 + 1], al[rh], bh1, bh3);
                }
            }
        }
        __syncthreads();
    }

    // epilogue: direct writes
    int qr = lane >> 2;
    int cb2 = (lane & 3) * 2;
    float amv[2][2], atv[2][2];
    if (MODE == 3) {
#pragma unroll
        for (int rh = 0; rh < 2; rh++)
#pragma unroll
            for (int q = 0; q < 2; q++) {
                int row = m0 + rb + rh * 16 + qr + q * 8;
                amv[rh][q] = ampp[row];
                atv[rh][q] = attp[row];
            }
    }
#pragma unroll
    for (int rh = 0; rh < 2; rh++)
#pragma unroll
        for (int g = 0; g < 4; g++) {
            int col0 = cb + (g >> 1) * 16 + (g & 1) * 8 + cb2;
            float b0 = __ldg(&bias[col0]), b1 = __ldg(&bias[col0 + 1]);
            float v0 = acc[rh][g][0] + b0, v1 = acc[rh][g][1] + b1;
            float v2 = acc[rh][g][2] + b0, v3 = acc[rh][g][3] + b1;
            size_t o0 = (size_t)(m0 + rb + rh * 16 + qr) * 128 + col0;
            size_t o8 = o0 + 8 * 128;
            if (MODE == 3) {
                float2 x00 = *(const float2*)(X0 + o0);
                float2 x08 = *(const float2*)(X0 + o8);
                float2 x10 = *(const float2*)(X1 + o0);
                float2 x18 = *(const float2*)(X1 + o8);
                v0 = x00.x + amv[rh][0] * x10.x + atv[rh][0] * acc[rh][g][0] + b0;
                v1 = x00.y + amv[rh][0] * x10.y + atv[rh][0] * acc[rh][g][1] + b1;
                v2 = x08.x + amv[rh][1] * x18.x + atv[rh][1] * acc[rh][g][2] + b0;
                v3 = x08.y + amv[rh][1] * x18.y + atv[rh][1] * acc[rh][g][3] + b1;
                uint32_t h01, l01, h23, l23;
                cvt2(v0, v1, h01, l01);
                cvt2(v2, v3, h23, l23);
                *(uint32_t*)(outh + o0) = h01; *(uint32_t*)(outl + o0) = l01;
                *(uint32_t*)(outh + o8) = h23; *(uint32_t*)(outl + o8) = l23;
            } else {
                if (MODE == 1) {
                    if (v0 < 0.f) v0 *= 0.01f;
                    if (v1 < 0.f) v1 *= 0.01f;
                    if (v2 < 0.f) v2 *= 0.01f;
                    if (v3 < 0.f) v3 *= 0.01f;
                }
                float2 p0 = {v0, v1}, p8 = {v2, v3};
                *(float2*)(outf + o0) = p0;
                *(float2*)(outf + o8) = p8;
            }
        }
}

// ---------------- aggregation ----------------
__global__ void __launch_bounds__(128) k_agg() {
    __shared__ int s_src[128];
    int v = blockIdx.x;
    int f = threadIdx.x;
    int beg = g_off[v], end = g_off[v + 1];
    float a = g_Ap[v * NH + f];
    float sum = 0.f, sq = 0.f, mx = -3.4e38f, mn = 3.4e38f;
    for (int base = beg; base < end; base += 128) {
        int n = min(128, end - base);
        if (f < n) s_src[f] = g_csr[base + f];
        __syncthreads();
        int e = 0;
        for (; e + 4 <= n; e += 4) {
            int i0 = s_src[e], i1 = s_src[e + 1], i2 = s_src[e + 2], i3 = s_src[e + 3];
            float h0 = a + g_Bp[i0 * NH + f];
            float h1 = a + g_Bp[i1 * NH + f];
            float h2 = a + g_Bp[i2 * NH + f];
            float h3 = a + g_Bp[i3 * NH + f];
            sum += h0 + h1 + h2 + h3;
            sq += h0 * h0 + h1 * h1 + h2 * h2 + h3 * h3;
            mx = fmaxf(mx, fmaxf(fmaxf(h0, h1), fmaxf(h2, h3)));
            mn = fminf(mn, fminf(fminf(h0, h1), fminf(h2, h3)));
        }
        for (; e < n; e++) {
            float h = a + g_Bp[s_src[e] * NH + f];
            sum += h; sq += h * h; mx = fmaxf(mx, h); mn = fminf(mn, h);
        }
        __syncthreads();
    }
    int d = end - beg;
    float degc = d > 0 ? (float)d : 1.f;
    float mean = sum / degc;
    float stdv = sqrtf(fmaxf(sq / degc - mean * mean, 0.f) + 1e-5f);
    if (d == 0) { mx = 0.f; mn = 0.f; }
    size_t fb = (size_t)v * KF;
    g_fh[fb + f] = g_sh[v * NH + f];
    g_fl[fb + f] = g_sl[v * NH + f];
    wsplit(&g_fh[fb + 128 + f], &g_fl[fb + 128 + f], mean);
    wsplit(&g_fh[fb + 256 + f], &g_fl[fb + 256 + f], stdv);
    wsplit(&g_fh[fb + 384 + f], &g_fl[fb + 384 + f], mx);
    wsplit(&g_fh[fb + 512 + f], &g_fl[fb + 512 + f], mn);
}

// ---------------- readout tail ----------------
__global__ void __launch_bounds__(256) k_readout(const float* __restrict__ r2w,
                                                 const float* __restrict__ r2b,
                                                 const float* __restrict__ r3w,
                                                 const float* __restrict__ r3b,
                                                 const float* __restrict__ tgt,
                                                 float* __restrict__ out) {
    __shared__ float w2[128 * 8];
    int t = threadIdx.x;
    for (int i = t; i < 128 * 8; i += 256) w2[i] = r2w[i];
    __syncthreads();
    int warp = t >> 5, lane = t & 31;
    int v = blockIdx.x * 8 + warp;
    const float* h1 = g_h1 + v * NH;
    float p[8] = {0, 0, 0, 0, 0, 0, 0, 0};
    for (int k = lane; k < 128; k += 32) {
        float hv = h1[k];
#pragma unroll
        for (int j = 0; j < 8; j++) p[j] += hv * w2[k * 8 + j];
    }
#pragma unroll
    for (int j = 0; j < 8; j++)
#pragma unroll
        for (int s = 16; s; s >>= 1) p[j] += __shfl_xor_sync(0xffffffffu, p[j], s);
    if (lane == 0) {
        float h2[8];
#pragma unroll
        for (int j = 0; j < 8; j++) {
            float x = p[j] + r2b[j];
            h2[j] = x < 0.f ? 0.01f * x : x;
        }
        float err = 0.f;
#pragma unroll
        for (int c = 0; c < 3; c++) {
            float o = r3b[c];
#pragma unroll
            for (int j = 0; j < 8; j++) o += h2[j] * r3w[j * 3 + c];
            if (o < 0.f) o *= 0.01f;
            out[v * 3 + c] = o;
            float dd = o - tgt[v * 3 + c];
            err += dd * dd;
        }
        atomicAdd(&g_lossb[v >> 8], err);
    }
}

__global__ void k_loss(float* __restrict__ out) {
    __shared__ float s[128];
    int b = threadIdx.x;
    float l = g_lossb[b] / (float)(NPG * 3);
    out[NV * 3 + 1 + b] = l;
    s[b] = l;
    __syncthreads();
    for (int d = 64; d; d >>= 1) {
        if (b < d) s[b] += s[b + d];
        __syncthreads();
    }
    if (b == 0) out[NV * 3] = s[0] / (float)NB;
}

// ---------------- host ----------------
template <typename T>
static void* symv(T& s) { void* p = nullptr; cudaGetSymbolAddress(&p, s); return p; }

extern "C" void kernel_launch(void* const* d_in, const int* in_sizes, int n_in,
                              void* d_out, int out_size) {
    const float* x       = (const float*)d_in[0];
    const int*   ei      = (const int*)d_in[1];
    const float* tgt_n   = (const float*)d_in[2];
    const float* pre1_w  = (const float*)d_in[4];
    const float* pre1_b  = (const float*)d_in[5];
    const float* post1_w = (const float*)d_in[6];
    const float* post1_b = (const float*)d_in[7];
    const float* lin1_w  = (const float*)d_in[8];
    const float* lin1_b  = (const float*)d_in[9];
    const float* pre_w   = (const float*)d_in[10];
    const float* pre_b   = (const float*)d_in[11];
    const float* post_w  = (const float*)d_in[12];
    const float* post_b  = (const float*)d_in[13];
    const float* lin_w   = (const float*)d_in[14];
    const float* lin_b   = (const float*)d_in[15];
    const float* r1_w    = (const float*)d_in[16];
    const float* r1_b    = (const float*)d_in[17];
    const float* r2_w    = (const float*)d_in[18];
    const float* r2_b    = (const float*)d_in[19];
    const float* r3_w    = (const float*)d_in[20];
    const float* r3_b    = (const float*)d_in[21];
    float* out = (float*)d_out;

    float* p_Ap  = (float*)symv(g_Ap);
    float* p_Bp  = (float*)symv(g_Bp);
    float* p_c0  = (float*)symv(g_c0);
    float* p_c1  = (float*)symv(g_c1);
    float* p_c2  = (float*)symv(g_c2);
    float* p_h1  = (float*)symv(g_h1);
    float* p_amp = (float*)symv(g_amp);
    float* p_att = (float*)symv(g_att);
    float* p_z   = (float*)symv(g_zero128);
    float* p_lbf  = (float*)symv(g_lbf);
    float* p_lb1f = (float*)symv(g_lb1f);
    u16* p_sh  = (u16*)symv(g_sh);   u16* p_sl  = (u16*)symv(g_sl);
    u16* p_fh  = (u16*)symv(g_fh);   u16* p_fl  = (u16*)symv(g_fl);
    u16* p_W0h = (u16*)symv(g_W0h);
    u16* p_W1h = (u16*)symv(g_W1h);
    u16* p_W2h = (u16*)symv(g_W2h);
    u16* p_WpAh = (u16*)symv(g_WpAh);
    u16* p_WpBh = (u16*)symv(g_WpBh);
    u16* p_Wr1h = (u16*)symv(g_Wr1h);

    const int SMG = 40960;   // double-buffered 2*20480
    cudaFuncSetAttribute(k_g<0>, cudaFuncAttributeMaxDynamicSharedMemorySize, SMG);
    cudaFuncSetAttribute(k_g<1>, cudaFuncAttributeMaxDynamicSharedMemorySize, SMG);
    cudaFuncSetAttribute(k_g<3>, cudaFuncAttributeMaxDynamicSharedMemorySize, SMG);

    // graph setup
    k_zero<<<NV / 256, 256>>>();
    k_hist<<<NE / 256, 256>>>(ei);
    k_scan<<<1, 1024>>>();
    k_scatter<<<NE / 256, 256>>>(ei);
    k_degstat<<<NV / 256, 256>>>();
    k_ampatt<<<NV / 256, 256>>>();

    // weight fusion (fp32): Wf_i = Wi @ lin_w; post1 fused with lin1; biases.
    k_wf<<<KF, 128>>>(post_w, lin_w, p_c0);
    k_wf<<<512, 128>>>(post_w + 640 * NH, lin_w, p_c1);
    k_wf<<<512, 128>>>(post_w + 1152 * NH, lin_w, p_c2);
    k_wf<<<26, 128>>>(post1_w, lin1_w, p_h1);
    k_bf<<<1, 128>>>(post_b, lin_w, lin_b, p_lbf);
    k_bf<<<1, 128>>>(post1_b, lin1_w, lin1_b, p_lb1f);

    // weight transposes -> single fp16 planes
    dim3 tb(32, 8);
    k_tsplit<<<dim3(4, 4), tb>>>(pre_w, p_WpAh, NH);
    k_tsplit<<<dim3(4, 4), tb>>>(pre_w + NH * NH, p_WpBh, NH);
    k_tsplit<<<dim3(KF / 32, 4), tb>>>(p_c0, p_W0h, KF);
    k_tsplit<<<dim3(16, 4), tb>>>(p_c1, p_W1h, 512);
    k_tsplit<<<dim3(16, 4), tb>>>(p_c2, p_W2h, 512);
    k_tsplit<<<dim3(4, 4), tb>>>(r1_w, p_Wr1h, NH);

    // layer 1 (post1 fused with lin1 -> state planes directly)
    k_pre1<<<NV / 256, 256>>>(x, pre1_w, pre1_b);
    k_agg1<<<NV / 256, 256>>>(x);
    k_post1<<<NV, 128>>>(p_h1, p_lb1f);

    // 3 propagation layers (lin eliminated; fp16 2-MMA GEMMs)
    for (int p = 0; p < 3; p++) {
        k_g<0><<<NV / 64, 256, SMG>>>(p_sh, p_sl, NH, NH, p_WpAh, pre_b,
                                      p_Ap, 0, 0, 0, 0, 0, 0);
        k_g<0><<<NV / 64, 256, SMG>>>(p_sh, p_sl, NH, NH, p_WpBh, p_z,
                                      p_Bp, 0, 0, 0, 0, 0, 0);
        k_agg<<<NV, 128>>>();
        k_g<0><<<NV / 64, 256, SMG>>>(p_fh, p_fl, KF, KF, p_W0h, p_z,
                                      p_c0, 0, 0, 0, 0, 0, 0);
        k_g<0><<<NV / 64, 256, SMG>>>(p_fh + 128, p_fl + 128, KF, 512,
                                      p_W1h, p_z, p_c1, 0, 0, 0, 0, 0, 0);
        k_g<3><<<NV / 64, 256, SMG>>>(p_fh + 128, p_fl + 128, KF, 512,
                                      p_W2h, p_lbf, 0, p_sh, p_sl,
                                      p_c0, p_c1, p_amp, p_att);
    }

    // readout
    k_g<1><<<NV / 64, 256, SMG>>>(p_sh, p_sl, NH, NH, p_Wr1h, r1_b,
                                  p_h1, 0, 0, 0, 0, 0, 0);
    k_readout<<<NV / 8, 256>>>(r2_w, r2_b, r3_w, r3_b, tgt_n, out);
    k_loss<<<1, 128>>>(out);

    (void)in_sizes; (void)n_in; (void)out_size;
}